// round 1
// baseline (speedup 1.0000x reference)
#include <cuda_runtime.h>

#define N_WL 262144
#define N_WL4 (N_WL / 4)

// Persistent scratch (no allocations allowed)
__device__ float  g_m2[64];
__device__ float  g_h[32];
__device__ float4 g_line[10];   // {nu0, 1/(sigma+eps), y, amp}

__device__ const float LNU0[10]  = {254.f, 280.f, 310.f, 940.f, 1130.f, 1380.f, 1400.f, 1600.f, 2000.f, 2700.f};
__device__ const float LSTR[10]  = {1.15e-17f, 5e-18f, 1.9e-19f, 2.5e-23f, 8.2e-24f, 1.8e-22f, 3.5e-25f, 7.8e-26f, 4.2e-24f, 1.2e-24f};
__device__ const float LWID[10]  = {2.0f, 3.0f, 2.5f, 3.0f, 2.5f, 4.0f, 3.0f, 2.5f, 4.0f, 3.5f};
__device__ const float LTE[10]   = {0.05f, 0.04f, 0.03f, 0.4f, 0.35f, 0.45f, 0.5f, 0.48f, 0.52f, 0.49f};
__device__ const float LMASS[10] = {48.f, 48.f, 48.f, 18.f, 18.f, 18.f, 44.f, 44.f, 44.f, 44.f};

// Voigt profile contribution for one line: amp * w(x, y)
__device__ __forceinline__ float voigt_line(float wl, float4 L) {
    float x  = (wl - L.x) * L.y;   // (wl - nu0) / (sigma + eps)
    float y  = L.z;
    float ax = fabsf(x);
    float s  = ax + y;
    float w;
    if (s >= 15.0f) {
        // w1 = Re( t * 0.5641896 / (0.5 + t^2) ), t = y - i x
        float t2r = y * y - x * x;
        float t2i = -2.0f * x * y;
        float dr  = 0.5f + t2r;
        float di  = t2i;
        float nr  = 0.5641896f * y;
        float ni  = 0.5641896f * (-x);
        w = (nr * dr + ni * di) / (dr * dr + di * di);
    } else if (ax >= 5.5f) {
        // w2 = Re( t*(1.410474 + u*0.5641896) / (0.75 + u*(3+u)) ), u = t^2
        float tr = y, ti = -x;
        float ur = y * y - x * x;
        float ui = -2.0f * x * y;
        float ar = 1.410474f + 0.5641896f * ur;
        float ai = 0.5641896f * ui;
        float nr = tr * ar - ti * ai;
        float ni = tr * ai + ti * ar;
        float u2r = ur * ur - ui * ui;
        float u2i = 2.0f * ur * ui;
        float dr = 0.75f + 3.0f * ur + u2r;
        float di = 3.0f * ui + u2i;
        w = (nr * dr + ni * di) / (dr * dr + di * di);
    } else {
        float xx = x * x;
        w = expf(-xx) * cosf(2.0f * x * y) * 0.5641896f
          + (2.0f * y / 3.14159265358979f) * sinf(xx) / (xx + y * y + 1e-10f);
    }
    return L.w * w;
}

__device__ __forceinline__ float softplus_f(float z) {
    return fmaxf(z, 0.0f) + log1pf(expf(-fabsf(z)));
}
__device__ __forceinline__ float silu_f(float z) {
    return z / (1.0f + expf(-z));
}

// ---------------------------------------------------------------------------
// Kernel A: tiny prep — line coefficients, h[32], cross[:8], m2[64]
// ---------------------------------------------------------------------------
__global__ void prep_kernel(
    const float* __restrict__ wl,
    const float* __restrict__ Tp,  const float* __restrict__ Pp,
    const float* __restrict__ o3p, const float* __restrict__ h2op, const float* __restrict__ co2p,
    const float* __restrict__ mix_w1,  const float* __restrict__ mix_b1,
    const float* __restrict__ mix_w2,  const float* __restrict__ mix_b2,
    const float* __restrict__ cont_w1, const float* __restrict__ cont_b1,
    const float* __restrict__ cont_w2, const float* __restrict__ cont_b2)
{
    __shared__ float4 s_line[10];
    __shared__ float  s_h[32];
    __shared__ float  s_feat[10];
    __shared__ float  s_m1[64];

    const int t = threadIdx.x;   // 64 threads
    const float T = Tp[0];
    const float P = Pp[0];

    if (t < 10) {
        float conc = (t < 3) ? o3p[0] : ((t < 6) ? h2op[0] : co2p[0]);
        float nu0  = LNU0[t];
        float sT   = LSTR[t] * powf(273.15f / (T + 1e-12f), LTE[t]);
        float gL   = LWID[t] * (P / 101325.0f) * sqrtf(273.15f / (T + 1e-12f));
        float g    = 2.0f * 1.380649e-23f * T;
        g *= 6.02214076e23f;
        g /= (LMASS[t] + 1e-12f);
        float gD    = nu0 / 2.99792458e8f * sqrtf(g);
        float sigma = gD / 1.1774100226f;                 // sqrt(2 ln 2)
        float inv_s = 1.0f / (sigma + 1e-12f);
        float y     = gL * inv_s;
        float amp   = conc * sT / (sigma * 1.7724538509f + 1e-12f);  // / (sigma*sqrt(pi)+eps)
        float4 L = make_float4(nu0, inv_s, y, amp);
        s_line[t] = L;
        g_line[t] = L;
    }
    if (t < 32) {
        // cont_feat = [T/Tref, P/Pref, conc_h2o, 1, 0]; cont_w1 is (5,32) row-major
        float f0 = T / 273.15f;
        float f1 = P / 101325.0f;
        float f2 = h2op[0];
        float z = cont_b1[t]
                + f0 * cont_w1[t]
                + f1 * cont_w1[32 + t]
                + f2 * cont_w1[64 + t]
                +      cont_w1[96 + t];    // feat[3] = 1, feat[4] = 0
        float h = silu_f(z);
        s_h[t] = h;
        g_h[t] = h;
    }
    if (t == 0) {
        s_feat[0] = T / 273.15f;
        s_feat[1] = P / 101325.0f;
    }
    __syncthreads();

    if (t < 8) {
        float w = wl[t];
        float cross = 0.0f;
        #pragma unroll
        for (int l = 0; l < 10; l++) cross += voigt_line(w, s_line[l]);
        float z = cont_b2[t];
        #pragma unroll
        for (int j = 0; j < 32; j++) z += s_h[j] * cont_w2[j * N_WL + t];
        s_feat[2 + t] = cross + softplus_f(z);
    }
    __syncthreads();

    // m1 = silu(feat @ mix_w1 + b1), mix_w1 is (10,64) row-major
    {
        float z = mix_b1[t];
        #pragma unroll
        for (int k = 0; k < 10; k++) z += s_feat[k] * mix_w1[k * 64 + t];
        s_m1[t] = silu_f(z);
    }
    __syncthreads();

    // m2 = silu(m1 @ mix_w2 + b2), mix_w2 is (64,64) row-major
    {
        float z = mix_b2[t];
        #pragma unroll
        for (int k = 0; k < 64; k++) z += s_m1[k] * mix_w2[k * 64 + t];
        g_m2[t] = silu_f(z);
    }
}

// ---------------------------------------------------------------------------
// Kernel B: streaming per-wavelength — dot(m2, w3_col) + dot(h, cw2_col)
//           + Voigt + activations. 4 wavelengths / thread (float4).
// ---------------------------------------------------------------------------
__global__ void __launch_bounds__(256) main_kernel(
    const float* __restrict__ wl,
    const float* __restrict__ mix_w3,  const float* __restrict__ mix_b3,
    const float* __restrict__ cont_w2, const float* __restrict__ cont_b2,
    float* __restrict__ out)
{
    __shared__ float  s_m2[64];
    __shared__ float  s_h[32];
    __shared__ float4 s_line[10];

    const int t = threadIdx.x;
    if (t < 64)           s_m2[t]        = g_m2[t];
    else if (t < 96)      s_h[t - 64]    = g_h[t - 64];
    else if (t < 106)     s_line[t - 96] = g_line[t - 96];
    __syncthreads();

    const int i = blockIdx.x * 256 + t;   // float4 index, < N_WL4

    const float4* __restrict__ w3 = (const float4*)mix_w3;
    const float4* __restrict__ cw = (const float4*)cont_w2;

    float4 am = make_float4(0.f, 0.f, 0.f, 0.f);
    #pragma unroll 16
    for (int r = 0; r < 64; r++) {
        float4 v = w3[r * N_WL4 + i];
        float  m = s_m2[r];
        am.x = fmaf(m, v.x, am.x);
        am.y = fmaf(m, v.y, am.y);
        am.z = fmaf(m, v.z, am.z);
        am.w = fmaf(m, v.w, am.w);
    }

    float4 ac = make_float4(0.f, 0.f, 0.f, 0.f);
    #pragma unroll 16
    for (int r = 0; r < 32; r++) {
        float4 v = cw[r * N_WL4 + i];
        float  h = s_h[r];
        ac.x = fmaf(h, v.x, ac.x);
        ac.y = fmaf(h, v.y, ac.y);
        ac.z = fmaf(h, v.z, ac.z);
        ac.w = fmaf(h, v.w, ac.w);
    }

    float4 wv = ((const float4*)wl)[i];
    float4 b3 = ((const float4*)mix_b3)[i];
    float4 cb = ((const float4*)cont_b2)[i];

    float wls[4] = {wv.x, wv.y, wv.z, wv.w};
    float zcs[4] = {ac.x + cb.x, ac.y + cb.y, ac.z + cb.z, ac.w + cb.w};
    float zms[4] = {am.x + b3.x, am.y + b3.y, am.z + b3.z, am.w + b3.w};
    float res[4];

    #pragma unroll
    for (int c = 0; c < 4; c++) {
        float cross = 0.0f;
        #pragma unroll
        for (int l = 0; l < 10; l++) cross += voigt_line(wls[c], s_line[l]);
        cross += softplus_f(zcs[c]);
        float mixing = 1.0f / (1.0f + expf(-zms[c]));
        res[c] = cross * (1.0f + 0.1f * (mixing - 0.5f));
    }

    ((float4*)out)[i] = make_float4(res[0], res[1], res[2], res[3]);
}

// ---------------------------------------------------------------------------
extern "C" void kernel_launch(void* const* d_in, const int* in_sizes, int n_in,
                              void* d_out, int out_size)
{
    const float* wl      = (const float*)d_in[0];
    const float* T       = (const float*)d_in[1];
    const float* P       = (const float*)d_in[2];
    const float* o3      = (const float*)d_in[3];
    const float* h2o     = (const float*)d_in[4];
    const float* co2     = (const float*)d_in[5];
    const float* mix_w1  = (const float*)d_in[6];
    const float* mix_b1  = (const float*)d_in[7];
    const float* mix_w2  = (const float*)d_in[8];
    const float* mix_b2  = (const float*)d_in[9];
    const float* mix_w3  = (const float*)d_in[10];
    const float* mix_b3  = (const float*)d_in[11];
    const float* cont_w1 = (const float*)d_in[12];
    const float* cont_b1 = (const float*)d_in[13];
    const float* cont_w2 = (const float*)d_in[14];
    const float* cont_b2 = (const float*)d_in[15];
    float* out = (float*)d_out;

    prep_kernel<<<1, 64>>>(wl, T, P, o3, h2o, co2,
                           mix_w1, mix_b1, mix_w2, mix_b2,
                           cont_w1, cont_b1, cont_w2, cont_b2);

    main_kernel<<<N_WL4 / 256, 256>>>(wl, mix_w3, mix_b3, cont_w2, cont_b2, out);
}